// round 2
// baseline (speedup 1.0000x reference)
#include <cuda_runtime.h>
#include <math.h>
#include <stdint.h>

#define BATCH 8
#define NBF   4194304   // 65536*64 floats per batch
typedef unsigned long long u64;

__device__ __forceinline__ u64 pack2(float x, float y) {
  u64 r; asm("mov.b64 %0, {%1, %2};" : "=l"(r) : "f"(x), "f"(y)); return r;
}
__device__ __forceinline__ void fma2(u64 &d, u64 a, u64 b) {
  asm("fma.rn.f32x2 %0, %1, %2, %0;" : "+l"(d) : "l"(a), "l"(b));
}
__device__ __forceinline__ float2 unpack2(u64 a) {
  float2 f; asm("mov.b64 {%0, %1}, %2;" : "=f"(f.x), "=f"(f.y) : "l"(a)); return f;
}

__device__ float g_part[BATCH * 128 * 4096];  // per-chunk partial G
__device__ float g_Mt[BATCH * 4096];          // M transposed: [e][c]
__device__ float g_Wpt[4096];                 // Wp transposed: [c2][j]

__device__ __forceinline__ void zero_acc(u64 acc[8][4]) {
#pragma unroll
  for (int r = 0; r < 8; r++)
#pragma unroll
    for (int c = 0; c < 4; c++) acc[r][c] = 0ULL;
}

// C[i0..i0+7][j0..j0+7] += sum_k As[k][i]*Bs[k][j]; both k-major 64-wide.
__device__ __forceinline__ void gemm8x8(const float* As, const float* Bs,
                                        int i0, int j0, u64 acc[8][4]) {
#pragma unroll 8
  for (int k = 0; k < 64; k++) {
    float4 a0 = *reinterpret_cast<const float4*>(As + k * 64 + i0);
    float4 a1 = *reinterpret_cast<const float4*>(As + k * 64 + i0 + 4);
    ulonglong2 b0 = *reinterpret_cast<const ulonglong2*>(Bs + k * 64 + j0);
    ulonglong2 b1 = *reinterpret_cast<const ulonglong2*>(Bs + k * 64 + j0 + 4);
    u64 ap[8];
    ap[0] = pack2(a0.x, a0.x); ap[1] = pack2(a0.y, a0.y);
    ap[2] = pack2(a0.z, a0.z); ap[3] = pack2(a0.w, a0.w);
    ap[4] = pack2(a1.x, a1.x); ap[5] = pack2(a1.y, a1.y);
    ap[6] = pack2(a1.z, a1.z); ap[7] = pack2(a1.w, a1.w);
#pragma unroll
    for (int r = 0; r < 8; r++) {
      fma2(acc[r][0], ap[r], b0.x);
      fma2(acc[r][1], ap[r], b0.y);
      fma2(acc[r][2], ap[r], b1.x);
      fma2(acc[r][3], ap[r], b1.y);
    }
  }
}

__device__ __forceinline__ void acc_to_f4(u64 acc[8][4], int r, float4& w0, float4& w1) {
  float2 v0 = unpack2(acc[r][0]), v1 = unpack2(acc[r][1]);
  float2 v2 = unpack2(acc[r][2]), v3 = unpack2(acc[r][3]);
  w0 = make_float4(v0.x, v0.y, v1.x, v1.y);
  w1 = make_float4(v2.x, v2.y, v3.x, v3.y);
}

// ---------------- Kernel A: partial G = X^T X over 512-row chunks ----------
__global__ void __launch_bounds__(64) kA(const float* __restrict__ x) {
  int b = blockIdx.x >> 7, chunk = blockIdx.x & 127;
  const float* Xc = x + (size_t)b * NBF + (size_t)chunk * 512 * 64;
  __shared__ __align__(16) float tile[4096];
  int t = threadIdx.x, i0 = (t >> 3) * 8, j0 = (t & 7) * 8;
  u64 acc[8][4]; zero_acc(acc);
  for (int s = 0; s < 8; s++) {
    __syncthreads();
    const float4* src = reinterpret_cast<const float4*>(Xc + s * 4096);
    float4* dst = reinterpret_cast<float4*>(tile);
#pragma unroll
    for (int i = 0; i < 16; i++) dst[t + 64 * i] = src[t + 64 * i];
    __syncthreads();
    gemm8x8(tile, tile, i0, j0, acc);
  }
  float* P = g_part + (size_t)blockIdx.x * 4096;
#pragma unroll
  for (int r = 0; r < 8; r++) {
    float4 w0, w1; acc_to_f4(acc, r, w0, w1);
    *reinterpret_cast<float4*>(P + (i0 + r) * 64 + j0) = w0;
    *reinterpret_cast<float4*>(P + (i0 + r) * 64 + j0 + 4) = w1;
  }
}

// ---------------- Kernel B: reduce G, attn, topk+softmax, M ----------------
__global__ void __launch_bounds__(256) kB(const float* __restrict__ wqkv,
                                          const float* __restrict__ wproj) {
  int b = blockIdx.x, t = threadIdx.x;
  __shared__ __align__(16) float sG[4096];  // later reused as attn
  __shared__ __align__(16) float sP[4096];
  __shared__ __align__(16) float sW[4096];
  // reduce 128 partials
  {
    float acc[16];
#pragma unroll
    for (int i = 0; i < 16; i++) acc[i] = 0.f;
    const float* pb = g_part + (size_t)b * 128 * 4096;
    for (int k = 0; k < 128; k++) {
      const float* pk = pb + k * 4096 + t;
#pragma unroll
      for (int i = 0; i < 16; i++) acc[i] += pk[i * 256];
    }
#pragma unroll
    for (int i = 0; i < 16; i++) sG[t + i * 256] = acc[i];
  }
  for (int i = t; i < 4096; i += 256) sW[i] = wqkv[4096 + i];  // Wk
  __syncthreads();
  // P[e,d] = sum_f G[e,f] Wk[d,f]
  {
    int e = t >> 2, d0 = (t & 3) * 16;
    float acc[16];
#pragma unroll
    for (int i = 0; i < 16; i++) acc[i] = 0.f;
    for (int f = 0; f < 64; f++) {
      float g = sG[e * 64 + f];
#pragma unroll
      for (int i = 0; i < 16; i++) acc[i] += g * sW[(d0 + i) * 64 + f];
    }
#pragma unroll
    for (int i = 0; i < 16; i++) sP[e * 64 + d0 + i] = acc[i];
  }
  __syncthreads();
  for (int i = t; i < 4096; i += 256) sW[i] = wqkv[8192 + i];  // Wv
  __syncthreads();
  // attn[c,d] = 0.125 * sum_e Wv[c,e] P[e,d]  -> into sG
  {
    int c = t >> 2, d0 = (t & 3) * 16;
    float acc[16];
#pragma unroll
    for (int i = 0; i < 16; i++) acc[i] = 0.f;
    for (int e = 0; e < 64; e++) {
      float wv = sW[c * 64 + e];
#pragma unroll
      for (int i = 0; i < 16; i++) acc[i] += wv * sP[e * 64 + d0 + i];
    }
#pragma unroll
    for (int i = 0; i < 16; i++) sG[c * 64 + d0 + i] = acc[i] * 0.125f;
  }
  __syncthreads();
  // drop 14 smallest per row, softmax over kept
  if (t < 64) {
    float* row = sG + t * 64;
    u64 drop = 0;
    for (int it = 0; it < 14; it++) {
      float mn = INFINITY; int mi = 0;
      for (int d = 0; d < 64; d++) {
        if ((drop >> d) & 1ULL) continue;
        float v = row[d];
        if (v < mn) { mn = v; mi = d; }
      }
      drop |= 1ULL << mi;
    }
    float mx = -INFINITY;
    for (int d = 0; d < 64; d++)
      if (!((drop >> d) & 1ULL)) mx = fmaxf(mx, row[d]);
    float sum = 0.f;
    for (int d = 0; d < 64; d++) {
      float e = ((drop >> d) & 1ULL) ? 0.f : expf(row[d] - mx);
      row[d] = e; sum += e;
    }
    float inv = 1.f / sum;
    for (int d = 0; d < 64; d++) row[d] *= inv;
  }
  __syncthreads();
  for (int i = t; i < 4096; i += 256) sW[i] = wqkv[i];  // Wq
  __syncthreads();
  // M[c,e] = sum_d attn[c,d] Wq[d,e]; store transposed g_Mt[b][e][c]
  {
    int c = t >> 2, e0 = (t & 3) * 16;
    float acc[16];
#pragma unroll
    for (int i = 0; i < 16; i++) acc[i] = 0.f;
    for (int d = 0; d < 64; d++) {
      float a = sG[c * 64 + d];
#pragma unroll
      for (int i = 0; i < 16; i++) acc[i] += a * sW[d * 64 + e0 + i];
    }
#pragma unroll
    for (int i = 0; i < 16; i++) g_Mt[b * 4096 + (e0 + i) * 64 + c] = acc[i];
  }
  if (b == 0)
    for (int i = t; i < 4096; i += 256) g_Wpt[i] = wproj[(i & 63) * 64 + (i >> 6)];
}

// ---------------- Kernel C: per (b,p): Y = M (Xblk^T Wp^T) + bp + x --------
__global__ void __launch_bounds__(64) kC(const float* __restrict__ x,
                                         const float* __restrict__ bproj,
                                         float* __restrict__ y) {
  int b = blockIdx.x >> 10, p = blockIdx.x & 1023;
  int t = threadIdx.x, i0 = (t >> 3) * 8, j0 = (t & 7) * 8;
  __shared__ __align__(16) float sX[4096];  // Xblk, then A_p
  __shared__ __align__(16) float sB[4096];  // Wp^T
  __shared__ __align__(16) float sM[4096];  // M^T
  const float4* xs = reinterpret_cast<const float4*>(x + (size_t)b * NBF + (size_t)p * 4096);
  const float4* ws = reinterpret_cast<const float4*>(g_Wpt);
  const float4* ms = reinterpret_cast<const float4*>(g_Mt + b * 4096);
#pragma unroll
  for (int i = 0; i < 16; i++) {
    reinterpret_cast<float4*>(sX)[t + 64 * i] = xs[t + 64 * i];
    reinterpret_cast<float4*>(sB)[t + 64 * i] = ws[t + 64 * i];
    reinterpret_cast<float4*>(sM)[t + 64 * i] = ms[t + 64 * i];
  }
  __syncthreads();
  u64 acc[8][4]; zero_acc(acc);
  gemm8x8(sX, sB, i0, j0, acc);   // A_p[e,j] = sum_c2 X[c2,e] WpT[c2,j]
  __syncthreads();
#pragma unroll
  for (int r = 0; r < 8; r++) {
    float4 w0, w1; acc_to_f4(acc, r, w0, w1);
    *reinterpret_cast<float4*>(sX + (i0 + r) * 64 + j0) = w0;
    *reinterpret_cast<float4*>(sX + (i0 + r) * 64 + j0 + 4) = w1;
  }
  __syncthreads();
  zero_acc(acc);
  gemm8x8(sM, sX, i0, j0, acc);   // OUT[c,j] = sum_e Mt[e,c] A_p[e,j]
  float4 bpa = *reinterpret_cast<const float4*>(bproj + j0);
  float4 bpb = *reinterpret_cast<const float4*>(bproj + j0 + 4);
  const float* xr = x + (size_t)b * NBF;
  float* yr = y + (size_t)b * NBF;
#pragma unroll
  for (int r = 0; r < 8; r++) {
    int c = i0 + r;
    size_t off = ((size_t)(c * 1024 + p) << 6) + j0;
    float4 x0 = *reinterpret_cast<const float4*>(xr + off);
    float4 x1 = *reinterpret_cast<const float4*>(xr + off + 4);
    float4 w0, w1; acc_to_f4(acc, r, w0, w1);
    w0.x += bpa.x + x0.x; w0.y += bpa.y + x0.y;
    w0.z += bpa.z + x0.z; w0.w += bpa.w + x0.w;
    w1.x += bpb.x + x1.x; w1.y += bpb.y + x1.y;
    w1.z += bpb.z + x1.z; w1.w += bpb.w + x1.w;
    *reinterpret_cast<float4*>(yr + off) = w0;
    *reinterpret_cast<float4*>(yr + off + 4) = w1;
  }
}

extern "C" void kernel_launch(void* const* d_in, const int* in_sizes, int n_in,
                              void* d_out, int out_size) {
  const float* x     = (const float*)d_in[0];
  const float* wqkv  = (const float*)d_in[1];
  const float* wproj = (const float*)d_in[2];
  const float* bproj = (const float*)d_in[3];
  float* y = (float*)d_out;
  kA<<<1024, 64>>>(x);
  kB<<<8, 256>>>(wqkv, wproj);
  kC<<<8192, 64>>>(x, bproj, y);
}

// round 3
// speedup vs baseline: 1.1272x; 1.1272x over previous
#include <cuda_runtime.h>
#include <math.h>
#include <stdint.h>

#define BATCH 8
#define NBF   4194304   // 65536*64 floats per batch
typedef unsigned long long u64;

__device__ __forceinline__ u64 pack2(float x, float y) {
  u64 r; asm("mov.b64 %0, {%1, %2};" : "=l"(r) : "f"(x), "f"(y)); return r;
}
__device__ __forceinline__ void fma2(u64 &d, u64 a, u64 b) {
  asm("fma.rn.f32x2 %0, %1, %2, %0;" : "+l"(d) : "l"(a), "l"(b));
}
__device__ __forceinline__ float2 unpack2(u64 a) {
  float2 f; asm("mov.b64 {%0, %1}, %2;" : "=f"(f.x), "=f"(f.y) : "l"(a)); return f;
}
__device__ __forceinline__ void cp16(void* smem, const void* gmem) {
  unsigned s = (unsigned)__cvta_generic_to_shared(smem);
  asm volatile("cp.async.cg.shared.global [%0], [%1], 16;" :: "r"(s), "l"(gmem));
}
__device__ __forceinline__ void cp_commit() { asm volatile("cp.async.commit_group;"); }
template<int N> __device__ __forceinline__ void cp_wait() {
  asm volatile("cp.async.wait_group %0;" :: "n"(N));
}

__device__ float g_part[BATCH * 128 * 4096];  // one partial G per kA block
__device__ float g_G[BATCH * 4096];           // reduced G
__device__ float g_Mt[BATCH * 4096];          // M transposed: [e][c]
__device__ float g_Wpt[4096];                 // Wp transposed: [c2][j]

__device__ __forceinline__ void zero_acc(u64 acc[16][4]) {
#pragma unroll
  for (int r = 0; r < 16; r++)
#pragma unroll
    for (int c = 0; c < 4; c++) acc[r][c] = 0ULL;
}

__device__ __forceinline__ void acc_row(const u64* a, float4& w0, float4& w1) {
  float2 v0 = unpack2(a[0]), v1 = unpack2(a[1]);
  float2 v2 = unpack2(a[2]), v3 = unpack2(a[3]);
  w0 = make_float4(v0.x, v0.y, v1.x, v1.y);
  w1 = make_float4(v2.x, v2.y, v3.x, v3.y);
}

// acc[i0..i0+15][j0..j0+7] += sum_{k=k0}^{k1-1} As[k][i] * Bs[k][j]
// Both operands k-major, 64 wide. 16x8 per-thread tile (one warp = 64x64).
__device__ __forceinline__ void gemm16x8(const float* __restrict__ As,
                                         const float* __restrict__ Bs,
                                         int i0, int j0, int k0, int k1,
                                         u64 acc[16][4]) {
#pragma unroll 4
  for (int k = k0; k < k1; k++) {
    float av[16];
    const float* a = As + k * 64 + i0;
    *reinterpret_cast<float4*>(av)      = *reinterpret_cast<const float4*>(a);
    *reinterpret_cast<float4*>(av + 4)  = *reinterpret_cast<const float4*>(a + 4);
    *reinterpret_cast<float4*>(av + 8)  = *reinterpret_cast<const float4*>(a + 8);
    *reinterpret_cast<float4*>(av + 12) = *reinterpret_cast<const float4*>(a + 12);
    ulonglong2 b0 = *reinterpret_cast<const ulonglong2*>(Bs + k * 64 + j0);
    ulonglong2 b1 = *reinterpret_cast<const ulonglong2*>(Bs + k * 64 + j0 + 4);
#pragma unroll
    for (int r = 0; r < 16; r++) {
      u64 ap = pack2(av[r], av[r]);
      fma2(acc[r][0], ap, b0.x);
      fma2(acc[r][1], ap, b0.y);
      fma2(acc[r][2], ap, b1.x);
      fma2(acc[r][3], ap, b1.y);
    }
  }
}

// ---------------- Kernel A: partial G = X^T X over 512-row chunks ----------
// 2 warps per block, split-k (each warp takes half the rows of each subtile),
// cp.async double-buffered tiles, in-block cross-warp reduce.
__global__ void __launch_bounds__(64) kA(const float* __restrict__ x) {
  int b = blockIdx.x >> 7, chunk = blockIdx.x & 127;
  const float* Xc = x + (size_t)b * NBF + (size_t)chunk * 32768;
  __shared__ __align__(16) float buf[2][4096];
  int t = threadIdx.x, w = t >> 5, lane = t & 31;
  int i0 = (lane >> 3) * 16, j0 = (lane & 7) * 8;
  int kw = w * 32;
  u64 acc[16][4]; zero_acc(acc);
#pragma unroll
  for (int q = 0; q < 16; q++) {
    int c16 = (t + 64 * q) * 4;
    cp16(&buf[0][c16], Xc + c16);
  }
  cp_commit();
  for (int s = 0; s < 8; s++) {
    __syncthreads();   // all warps done reading buf[(s+1)&1] from iter s-1
    if (s < 7) {
      const float* src = Xc + (s + 1) * 4096;
      float* dst = buf[(s + 1) & 1];
#pragma unroll
      for (int q = 0; q < 16; q++) {
        int c16 = (t + 64 * q) * 4;
        cp16(dst + c16, src + c16);
      }
      cp_commit();
      cp_wait<1>();
    } else {
      cp_wait<0>();
    }
    __syncthreads();   // tile s resident
    gemm16x8(buf[s & 1], buf[s & 1], i0, j0, kw, kw + 32, acc);
  }
  // cross-warp reduce via the two buffers
#pragma unroll
  for (int r = 0; r < 16; r++) {
    float4 w0, w1; acc_row(acc[r], w0, w1);
    *reinterpret_cast<float4*>(&buf[w][(i0 + r) * 64 + j0])     = w0;
    *reinterpret_cast<float4*>(&buf[w][(i0 + r) * 64 + j0 + 4]) = w1;
  }
  __syncthreads();
  float4* P = reinterpret_cast<float4*>(g_part + (size_t)blockIdx.x * 4096);
  const float4* b0 = reinterpret_cast<const float4*>(buf[0]);
  const float4* b1 = reinterpret_cast<const float4*>(buf[1]);
#pragma unroll
  for (int q = 0; q < 16; q++) {
    int idx = t + 64 * q;
    float4 u = b0[idx], v = b1[idx];
    P[idx] = make_float4(u.x + v.x, u.y + v.y, u.z + v.z, u.w + v.w);
  }
}

// ---------------- kRed: reduce 128 partials per batch ----------------------
__global__ void __launch_bounds__(256) kRed() {
  int b = blockIdx.x >> 4, s = blockIdx.x & 15;
  int e = s * 256 + threadIdx.x;
  const float* P = g_part + (size_t)b * 128 * 4096 + e;
  float sum = 0.f;
#pragma unroll 8
  for (int k = 0; k < 128; k++) sum += P[(size_t)k * 4096];
  g_G[b * 4096 + e] = sum;
}

// ---------------- Kernel B: attn, topk+softmax, M ---------------------------
__global__ void __launch_bounds__(256) kB(const float* __restrict__ wqkv,
                                          const float* __restrict__ wproj) {
  int b = blockIdx.x, t = threadIdx.x;
  __shared__ __align__(16) float sG[4096];  // later reused as attn
  __shared__ __align__(16) float sP[4096];
  __shared__ __align__(16) float sW[4096];
  for (int i = t; i < 4096; i += 256) sG[i] = g_G[b * 4096 + i];
  for (int i = t; i < 4096; i += 256) sW[i] = wqkv[4096 + i];  // Wk
  __syncthreads();
  // P[e,d] = sum_f G[e,f] Wk[d,f]
  {
    int e = t >> 2, d0 = (t & 3) * 16;
    float acc[16];
#pragma unroll
    for (int i = 0; i < 16; i++) acc[i] = 0.f;
    for (int f = 0; f < 64; f++) {
      float g = sG[e * 64 + f];
#pragma unroll
      for (int i = 0; i < 16; i++) acc[i] += g * sW[(d0 + i) * 64 + f];
    }
#pragma unroll
    for (int i = 0; i < 16; i++) sP[e * 64 + d0 + i] = acc[i];
  }
  __syncthreads();
  for (int i = t; i < 4096; i += 256) sW[i] = wqkv[8192 + i];  // Wv
  __syncthreads();
  // attn[c,d] = 0.125 * sum_e Wv[c,e] P[e,d]  -> into sG
  {
    int c = t >> 2, d0 = (t & 3) * 16;
    float acc[16];
#pragma unroll
    for (int i = 0; i < 16; i++) acc[i] = 0.f;
    for (int e = 0; e < 64; e++) {
      float wv = sW[c * 64 + e];
#pragma unroll
      for (int i = 0; i < 16; i++) acc[i] += wv * sP[e * 64 + d0 + i];
    }
#pragma unroll
    for (int i = 0; i < 16; i++) sG[c * 64 + d0 + i] = acc[i] * 0.125f;
  }
  __syncthreads();
  // drop 14 smallest per row, softmax over kept
  if (t < 64) {
    float* row = sG + t * 64;
    u64 drop = 0;
    for (int it = 0; it < 14; it++) {
      float mn = INFINITY; int mi = 0;
      for (int d = 0; d < 64; d++) {
        if ((drop >> d) & 1ULL) continue;
        float v = row[d];
        if (v < mn) { mn = v; mi = d; }
      }
      drop |= 1ULL << mi;
    }
    float mx = -INFINITY;
    for (int d = 0; d < 64; d++)
      if (!((drop >> d) & 1ULL)) mx = fmaxf(mx, row[d]);
    float sum = 0.f;
    for (int d = 0; d < 64; d++) {
      float e = ((drop >> d) & 1ULL) ? 0.f : expf(row[d] - mx);
      row[d] = e; sum += e;
    }
    float inv = 1.f / sum;
    for (int d = 0; d < 64; d++) row[d] *= inv;
  }
  __syncthreads();
  for (int i = t; i < 4096; i += 256) sW[i] = wqkv[i];  // Wq
  __syncthreads();
  // M[c,e] = sum_d attn[c,d] Wq[d,e]; store transposed g_Mt[b][e][c]
  {
    int c = t >> 2, e0 = (t & 3) * 16;
    float acc[16];
#pragma unroll
    for (int i = 0; i < 16; i++) acc[i] = 0.f;
    for (int d = 0; d < 64; d++) {
      float a = sG[c * 64 + d];
#pragma unroll
      for (int i = 0; i < 16; i++) acc[i] += a * sW[d * 64 + e0 + i];
    }
#pragma unroll
    for (int i = 0; i < 16; i++) g_Mt[b * 4096 + (e0 + i) * 64 + c] = acc[i];
  }
  if (b == 0)
    for (int i = t; i < 4096; i += 256) g_Wpt[i] = wproj[(i & 63) * 64 + (i >> 6)];
}

// ---------------- Kernel C: per (b,p): Y = M (Xblk^T Wp^T) + bp + x ---------
// 4 warps per block = 4 independent p-blocks sharing one smem copy of Wp^T/M^T.
__global__ void __launch_bounds__(128) kC(const float* __restrict__ x,
                                          const float* __restrict__ bproj,
                                          float* __restrict__ y) {
  int b = blockIdx.x >> 8, pg = blockIdx.x & 255;
  int t = threadIdx.x, w = t >> 5, lane = t & 31;
  int p = pg * 4 + w;
  int i0 = (lane >> 3) * 16, j0 = (lane & 7) * 8;
  __shared__ __align__(16) float sB[4096];
  __shared__ __align__(16) float sM[4096];
  __shared__ __align__(16) float sX[4][4096];
  {
    const float4* wb = reinterpret_cast<const float4*>(g_Wpt);
    const float4* wm = reinterpret_cast<const float4*>(g_Mt + b * 4096);
    float4* db = reinterpret_cast<float4*>(sB);
    float4* dm = reinterpret_cast<float4*>(sM);
#pragma unroll
    for (int q = 0; q < 8; q++) {
      db[t + 128 * q] = wb[t + 128 * q];
      dm[t + 128 * q] = wm[t + 128 * q];
    }
  }
  {
    const float* src = x + (size_t)b * NBF + (size_t)p * 4096;
    float* dst = sX[w];
#pragma unroll
    for (int q = 0; q < 32; q++) {
      int c16 = (lane + 32 * q) * 4;
      cp16(dst + c16, src + c16);
    }
    cp_commit();
    cp_wait<0>();
  }
  __syncthreads();
  u64 acc[16][4];
  zero_acc(acc);
  gemm16x8(sX[w], sB, i0, j0, 0, 64, acc);   // A[e,j] = sum_c2 X[c2,e] WpT[c2,j]
  __syncwarp();
#pragma unroll
  for (int r = 0; r < 16; r++) {
    float4 w0, w1; acc_row(acc[r], w0, w1);
    *reinterpret_cast<float4*>(sX[w] + (i0 + r) * 64 + j0)     = w0;
    *reinterpret_cast<float4*>(sX[w] + (i0 + r) * 64 + j0 + 4) = w1;
  }
  __syncwarp();
  zero_acc(acc);
  gemm16x8(sM, sX[w], i0, j0, 0, 64, acc);   // OUT[c,j] = sum_e Mt[e,c] A[e,j]
  float4 bpa = *reinterpret_cast<const float4*>(bproj + j0);
  float4 bpb = *reinterpret_cast<const float4*>(bproj + j0 + 4);
  const float* xr = x + (size_t)b * NBF;
  float* yr = y + (size_t)b * NBF;
#pragma unroll
  for (int r = 0; r < 16; r++) {
    int c = i0 + r;
    size_t off = ((size_t)(c * 1024 + p) << 6) + j0;
    float4 x0 = *reinterpret_cast<const float4*>(xr + off);
    float4 x1 = *reinterpret_cast<const float4*>(xr + off + 4);
    float4 w0, w1; acc_row(acc[r], w0, w1);
    w0.x += bpa.x + x0.x; w0.y += bpa.y + x0.y;
    w0.z += bpa.z + x0.z; w0.w += bpa.w + x0.w;
    w1.x += bpb.x + x1.x; w1.y += bpb.y + x1.y;
    w1.z += bpb.z + x1.z; w1.w += bpb.w + x1.w;
    *reinterpret_cast<float4*>(yr + off)     = w0;
    *reinterpret_cast<float4*>(yr + off + 4) = w1;
  }
}

extern "C" void kernel_launch(void* const* d_in, const int* in_sizes, int n_in,
                              void* d_out, int out_size) {
  const float* x     = (const float*)d_in[0];
  const float* wqkv  = (const float*)d_in[1];
  const float* wproj = (const float*)d_in[2];
  const float* bproj = (const float*)d_in[3];
  float* y = (float*)d_out;
  kA<<<1024, 64>>>(x);
  kRed<<<128, 256>>>();
  kB<<<8, 256>>>(wqkv, wproj);
  kC<<<2048, 128>>>(x, bproj, y);
}

// round 5
// speedup vs baseline: 1.2968x; 1.1505x over previous
#include <cuda_runtime.h>
#include <math.h>
#include <stdint.h>

#define BATCH 8
#define NBF   4194304   // 65536*64 floats per batch
typedef unsigned long long u64;

// ---------------- async copy helpers -----------------------------------------
__device__ __forceinline__ void cp16(void* smem, const void* gmem) {
  unsigned s = (unsigned)__cvta_generic_to_shared(smem);
  asm volatile("cp.async.cg.shared.global [%0], [%1], 16;" :: "r"(s), "l"(gmem));
}
__device__ __forceinline__ void cp_commit() { asm volatile("cp.async.commit_group;"); }
template<int N> __device__ __forceinline__ void cp_wait() {
  asm volatile("cp.async.wait_group %0;" :: "n"(N));
}

// ---------------- tf32 mma helpers --------------------------------------------
__device__ __forceinline__ uint32_t cvt_tf32(float f) {
  uint32_t r; asm("cvt.rna.tf32.f32 %0, %1;" : "=r"(r) : "f"(f)); return r;
}
__device__ __forceinline__ void mma8(float* c, const uint32_t* a, const uint32_t* b) {
  asm volatile(
      "mma.sync.aligned.m16n8k8.row.col.f32.tf32.tf32.f32 "
      "{%0,%1,%2,%3}, {%4,%5,%6,%7}, {%8,%9}, {%0,%1,%2,%3};"
      : "+f"(c[0]), "+f"(c[1]), "+f"(c[2]), "+f"(c[3])
      : "r"(a[0]), "r"(a[1]), "r"(a[2]), "r"(a[3]), "r"(b[0]), "r"(b[1]));
}

#define ZERO_ACC(acc) \
  _Pragma("unroll") for (int _m = 0; _m < 4; _m++) \
  _Pragma("unroll") for (int _n = 0; _n < 8; _n++) \
  _Pragma("unroll") for (int _q = 0; _q < 4; _q++) (acc)[_m][_n][_q] = 0.f;

// C[m][n] += sum_k Am[k][m]*Bm[k][n]; Am,Bm k-major, row stride 72 floats.
// One warp computes the full 64x64 output; ktiles [kt0,kt1), 8 k per tile.
__device__ __forceinline__ void wgemm_bb(const float* Am, const float* Bm,
                                         int kt0, int kt1, float acc[4][8][4]) {
  int lane = threadIdx.x & 31, g = lane >> 2, t4 = lane & 3;
  for (int kt = kt0; kt < kt1; kt++) {
    const float* a_lo = Am + (kt * 8 + t4) * 72;
    const float* a_hi = a_lo + 4 * 72;
    uint32_t a[4][4], b[8][2];
#pragma unroll
    for (int mt = 0; mt < 4; mt++) {
      int m = mt * 16 + g;
      a[mt][0] = cvt_tf32(a_lo[m]);
      a[mt][1] = cvt_tf32(a_lo[m + 8]);
      a[mt][2] = cvt_tf32(a_hi[m]);
      a[mt][3] = cvt_tf32(a_hi[m + 8]);
    }
    const float* b_lo = Bm + (kt * 8 + t4) * 72;
    const float* b_hi = b_lo + 4 * 72;
#pragma unroll
    for (int nt = 0; nt < 8; nt++) {
      b[nt][0] = cvt_tf32(b_lo[nt * 8 + g]);
      b[nt][1] = cvt_tf32(b_hi[nt * 8 + g]);
    }
#pragma unroll
    for (int mt = 0; mt < 4; mt++)
#pragma unroll
      for (int nt = 0; nt < 8; nt++) mma8(acc[mt][nt], a[mt], b[nt]);
  }
}

// C[m][n] += sum_k Am[m][k]*Bm[k][n]; Am row-major stride 68, Bm k-major stride 72.
__device__ __forceinline__ void wgemm_ab(const float* Am, const float* Bm,
                                         float acc[4][8][4]) {
  int lane = threadIdx.x & 31, g = lane >> 2, t4 = lane & 3;
  for (int kt = 0; kt < 8; kt++) {
    uint32_t a[4][4], b[8][2];
#pragma unroll
    for (int mt = 0; mt < 4; mt++) {
      const float* r_lo = Am + (mt * 16 + g) * 68 + kt * 8;
      const float* r_hi = r_lo + 8 * 68;
      a[mt][0] = cvt_tf32(r_lo[t4]);
      a[mt][1] = cvt_tf32(r_hi[t4]);
      a[mt][2] = cvt_tf32(r_lo[t4 + 4]);
      a[mt][3] = cvt_tf32(r_hi[t4 + 4]);
    }
    const float* b_lo = Bm + (kt * 8 + t4) * 72;
    const float* b_hi = b_lo + 4 * 72;
#pragma unroll
    for (int nt = 0; nt < 8; nt++) {
      b[nt][0] = cvt_tf32(b_lo[nt * 8 + g]);
      b[nt][1] = cvt_tf32(b_hi[nt * 8 + g]);
    }
#pragma unroll
    for (int mt = 0; mt < 4; mt++)
#pragma unroll
      for (int nt = 0; nt < 8; nt++) mma8(acc[mt][nt], a[mt], b[nt]);
  }
}

// ---------------- scratch globals ---------------------------------------------
__device__ float g_part[BATCH * 128 * 4096];
__device__ float g_G[BATCH * 4096];
__device__ float g_M[BATCH * 4096];   // M natural: [c][e]
__device__ float g_Wpt[4096];         // Wp transposed: [c2][j]

// ---------------- kA: partial G = X^T X (tf32 mma) -----------------------------
__global__ void __launch_bounds__(64) kA(const float* __restrict__ x) {
  int b = blockIdx.x >> 7, chunk = blockIdx.x & 127;
  const float* Xc = x + (size_t)b * NBF + (size_t)chunk * 32768;
  __shared__ __align__(16) float buf[2][64 * 72];
  int t = threadIdx.x, w = t >> 5, lane = t & 31, g = lane >> 2, t4 = lane & 3;
  float acc[4][8][4];
  ZERO_ACC(acc);
#pragma unroll
  for (int q = 0; q < 16; q++) {
    int id = q * 64 + t;
    cp16(&buf[0][(id >> 4) * 72 + (id & 15) * 4], Xc + 4 * id);
  }
  cp_commit();
  for (int s = 0; s < 8; s++) {
    __syncthreads();
    if (s < 7) {
      const float* src = Xc + (s + 1) * 4096;
      float* dst = buf[(s + 1) & 1];
#pragma unroll
      for (int q = 0; q < 16; q++) {
        int id = q * 64 + t;
        cp16(&dst[(id >> 4) * 72 + (id & 15) * 4], src + 4 * id);
      }
      cp_commit();
      cp_wait<1>();
    } else {
      cp_wait<0>();
    }
    __syncthreads();
    wgemm_bb(buf[s & 1], buf[s & 1], 4 * w, 4 * w + 4, acc);
  }
  __syncthreads();  // done reading both buffers
  // park each warp's 64x64 result (stride 72) for cross-warp reduce
#pragma unroll
  for (int mt = 0; mt < 4; mt++)
#pragma unroll
    for (int nt = 0; nt < 8; nt++) {
      int col = nt * 8 + 2 * t4;
      *reinterpret_cast<float2*>(&buf[w][(mt * 16 + g) * 72 + col]) =
          make_float2(acc[mt][nt][0], acc[mt][nt][1]);
      *reinterpret_cast<float2*>(&buf[w][(mt * 16 + g + 8) * 72 + col]) =
          make_float2(acc[mt][nt][2], acc[mt][nt][3]);
    }
  __syncthreads();
  float* P = g_part + (size_t)blockIdx.x * 4096;
#pragma unroll 8
  for (int q = 0; q < 64; q++)
    P[q * 64 + t] = buf[0][q * 72 + t] + buf[1][q * 72 + t];
}

// ---------------- kRed: reduce 128 partials per batch ---------------------------
__global__ void __launch_bounds__(256) kRed() {
  int b = blockIdx.x >> 4, s = blockIdx.x & 15;
  int e = s * 256 + threadIdx.x;
  const float* P = g_part + (size_t)b * 128 * 4096 + e;
  float sum = 0.f;
#pragma unroll 8
  for (int k = 0; k < 128; k++) sum += P[(size_t)k * 4096];
  g_G[b * 4096 + e] = sum;
}

// ---------------- kB: attn, topk+softmax, M (fp32, exact) -----------------------
__global__ void __launch_bounds__(256) kB(const float* __restrict__ wqkv,
                                          const float* __restrict__ wproj) {
  int b = blockIdx.x, t = threadIdx.x;
  __shared__ __align__(16) float sG[4096];
  __shared__ __align__(16) float sP[4096];
  __shared__ __align__(16) float sW[4096];
  for (int i = t; i < 4096; i += 256) sG[i] = g_G[b * 4096 + i];
  for (int i = t; i < 4096; i += 256) sW[i] = wqkv[4096 + i];  // Wk
  __syncthreads();
  {
    int e = t >> 2, d0 = (t & 3) * 16;
    float acc[16];
#pragma unroll
    for (int i = 0; i < 16; i++) acc[i] = 0.f;
    for (int f = 0; f < 64; f++) {
      float gg = sG[e * 64 + f];
#pragma unroll
      for (int i = 0; i < 16; i++) acc[i] += gg * sW[(d0 + i) * 64 + f];
    }
#pragma unroll
    for (int i = 0; i < 16; i++) sP[e * 64 + d0 + i] = acc[i];
  }
  __syncthreads();
  for (int i = t; i < 4096; i += 256) sW[i] = wqkv[8192 + i];  // Wv
  __syncthreads();
  {
    int c = t >> 2, d0 = (t & 3) * 16;
    float acc[16];
#pragma unroll
    for (int i = 0; i < 16; i++) acc[i] = 0.f;
    for (int e = 0; e < 64; e++) {
      float wv = sW[c * 64 + e];
#pragma unroll
      for (int i = 0; i < 16; i++) acc[i] += wv * sP[e * 64 + d0 + i];
    }
#pragma unroll
    for (int i = 0; i < 16; i++) sG[c * 64 + d0 + i] = acc[i] * 0.125f;
  }
  __syncthreads();
  if (t < 64) {
    float* row = sG + t * 64;
    u64 drop = 0;
    for (int it = 0; it < 14; it++) {
      float mn = INFINITY; int mi = 0;
      for (int d = 0; d < 64; d++) {
        if ((drop >> d) & 1ULL) continue;
        float v = row[d];
        if (v < mn) { mn = v; mi = d; }
      }
      drop |= 1ULL << mi;
    }
    float mx = -INFINITY;
    for (int d = 0; d < 64; d++)
      if (!((drop >> d) & 1ULL)) mx = fmaxf(mx, row[d]);
    float sum = 0.f;
    for (int d = 0; d < 64; d++) {
      float e = ((drop >> d) & 1ULL) ? 0.f : expf(row[d] - mx);
      row[d] = e; sum += e;
    }
    float inv = 1.f / sum;
    for (int d = 0; d < 64; d++) row[d] *= inv;
  }
  __syncthreads();
  for (int i = t; i < 4096; i += 256) sW[i] = wqkv[i];  // Wq
  __syncthreads();
  {
    int c = t >> 2, e0 = (t & 3) * 16;
    float acc[16];
#pragma unroll
    for (int i = 0; i < 16; i++) acc[i] = 0.f;
    for (int d = 0; d < 64; d++) {
      float a = sG[c * 64 + d];
#pragma unroll
      for (int i = 0; i < 16; i++) acc[i] += a * sW[d * 64 + e0 + i];
    }
#pragma unroll
    for (int i = 0; i < 16; i++) g_M[b * 4096 + c * 64 + e0 + i] = acc[i];
  }
  if (b == 0)
    for (int i = t; i < 4096; i += 256) g_Wpt[i] = wproj[(i & 63) * 64 + (i >> 6)];
}

// ---------------- kC: per (b,p): Y = M (Xblk^T Wp^T) + bp + x (tf32 mma) --------
// 128 threads = 4 warps, each warp owns one p-block end-to-end.
// smem floats: Xs[4][64*72] | sWp[64*72] | sM[64*68]  -> 109568 bytes
#define KC_SMEM_FLOATS (4 * 4608 + 4608 + 4352)
__global__ void __launch_bounds__(128) kC(const float* __restrict__ x,
                                          const float* __restrict__ bproj,
                                          float* __restrict__ y) {
  extern __shared__ __align__(16) float s[];
  int t = threadIdx.x, w = t >> 5, lane = t & 31, g = lane >> 2, t4 = lane & 3;
  int b = blockIdx.x >> 8, pg = blockIdx.x & 255, p = pg * 4 + w;
  float* Xs  = s + w * 4608;
  float* sWp = s + 18432;
  float* sM  = s + 23040;
  const float* xg = x + (size_t)b * NBF + (size_t)p * 4096;
#pragma unroll
  for (int q = 0; q < 32; q++) {
    int id = q * 32 + lane;
    cp16(Xs + (id >> 4) * 72 + (id & 15) * 4, xg + 4 * id);
  }
  cp_commit();
#pragma unroll 4
  for (int q = 0; q < 32; q++) {
    int id = q * 128 + t;
    sWp[(id >> 6) * 72 + (id & 63)] = g_Wpt[id];
  }
#pragma unroll 4
  for (int q = 0; q < 32; q++) {
    int id = q * 128 + t;
    sM[(id >> 6) * 68 + (id & 63)] = g_M[b * 4096 + id];
  }
  cp_wait<0>();
  __syncthreads();

  float acc[4][8][4];
  ZERO_ACC(acc);
  wgemm_bb(Xs, sWp, 0, 8, acc);    // D1[e][j] = sum_c2 Xblk[c2][e] * WpT[c2][j]
  __syncwarp();
#pragma unroll
  for (int mt = 0; mt < 4; mt++)
#pragma unroll
    for (int nt = 0; nt < 8; nt++) {
      int col = nt * 8 + 2 * t4;
      *reinterpret_cast<float2*>(&Xs[(mt * 16 + g) * 72 + col]) =
          make_float2(acc[mt][nt][0], acc[mt][nt][1]);
      *reinterpret_cast<float2*>(&Xs[(mt * 16 + g + 8) * 72 + col]) =
          make_float2(acc[mt][nt][2], acc[mt][nt][3]);
    }
  __syncwarp();
  ZERO_ACC(acc);
  wgemm_ab(sM, Xs, acc);           // OUT[c][j] = sum_e M[c][e] * D1[e][j]

  const float* xr = x + (size_t)b * NBF;
  float* yr = y + (size_t)b * NBF;
#pragma unroll
  for (int nt = 0; nt < 8; nt++) {
    int j0 = nt * 8 + 2 * t4;
    float2 bp = *reinterpret_cast<const float2*>(bproj + j0);
#pragma unroll
    for (int mt = 0; mt < 4; mt++) {
      int c = mt * 16 + g;
      size_t off = ((size_t)(c * 1024 + p) << 6) + j0;
      float2 xv = *reinterpret_cast<const float2*>(xr + off);
      *reinterpret_cast<float2*>(yr + off) =
          make_float2(acc[mt][nt][0] + bp.x + xv.x, acc[mt][nt][1] + bp.y + xv.y);
      size_t off2 = ((size_t)((c + 8) * 1024 + p) << 6) + j0;
      float2 xv2 = *reinterpret_cast<const float2*>(xr + off2);
      *reinterpret_cast<float2*>(yr + off2) =
          make_float2(acc[mt][nt][2] + bp.x + xv2.x, acc[mt][nt][3] + bp.y + xv2.y);
    }
  }
}

extern "C" void kernel_launch(void* const* d_in, const int* in_sizes, int n_in,
                              void* d_out, int out_size) {
  const float* x     = (const float*)d_in[0];
  const float* wqkv  = (const float*)d_in[1];
  const float* wproj = (const float*)d_in[2];
  const float* bproj = (const float*)d_in[3];
  float* y = (float*)d_out;
  static int smem_set = 0;
  if (!smem_set) {
    cudaFuncSetAttribute(kC, cudaFuncAttributeMaxDynamicSharedMemorySize,
                         KC_SMEM_FLOATS * 4);
    smem_set = 1;
  }
  kA<<<1024, 64>>>(x);
  kRed<<<128, 256>>>();
  kB<<<8, 256>>>(wqkv, wproj);
  kC<<<2048, 128, KC_SMEM_FLOATS * 4>>>(x, bproj, y);
}

// round 6
// speedup vs baseline: 1.4073x; 1.0852x over previous
#include <cuda_runtime.h>
#include <math.h>
#include <stdint.h>

#define BATCH 8
#define NBF   4194304   // 65536*64 floats per batch
typedef unsigned long long u64;

// ---------------- async copy helpers -----------------------------------------
__device__ __forceinline__ void cp16(void* smem, const void* gmem) {
  unsigned s = (unsigned)__cvta_generic_to_shared(smem);
  asm volatile("cp.async.cg.shared.global [%0], [%1], 16;" :: "r"(s), "l"(gmem));
}
__device__ __forceinline__ void cp_commit() { asm volatile("cp.async.commit_group;"); }
template<int N> __device__ __forceinline__ void cp_wait() {
  asm volatile("cp.async.wait_group %0;" :: "n"(N));
}

// ---------------- tf32 mma helpers --------------------------------------------
__device__ __forceinline__ uint32_t cvt_tf32(float f) {
  uint32_t r; asm("cvt.rna.tf32.f32 %0, %1;" : "=r"(r) : "f"(f)); return r;
}
__device__ __forceinline__ void mma8(float* c, const uint32_t* a, const uint32_t* b) {
  asm volatile(
      "mma.sync.aligned.m16n8k8.row.col.f32.tf32.tf32.f32 "
      "{%0,%1,%2,%3}, {%4,%5,%6,%7}, {%8,%9}, {%0,%1,%2,%3};"
      : "+f"(c[0]), "+f"(c[1]), "+f"(c[2]), "+f"(c[3])
      : "r"(a[0]), "r"(a[1]), "r"(a[2]), "r"(a[3]), "r"(b[0]), "r"(b[1]));
}
__device__ __forceinline__ uint32_t frag_ld(const float* p)    { return cvt_tf32(*p); }
__device__ __forceinline__ uint32_t frag_ld(const uint32_t* p) { return *p; }

#define ZERO_ACC4(acc) \
  _Pragma("unroll") for (int _m = 0; _m < 4; _m++) \
  _Pragma("unroll") for (int _n = 0; _n < 4; _n++) \
  _Pragma("unroll") for (int _q = 0; _q < 4; _q++) (acc)[_m][_n][_q] = 0.f;

// C[m=0..63][n=0..31] += sum_k A[k][m] * B[k][n]; A,B k-major stride 72.
// 4 k-tiles starting at ktbase (32 k values).
template<typename TA, typename TB>
__device__ __forceinline__ void wgemm_k72(const TA* Am, const TB* Bm,
                                          int ktbase, float acc[4][4][4]) {
  int lane = threadIdx.x & 31, g = lane >> 2, t4 = lane & 3;
#pragma unroll
  for (int ki = 0; ki < 4; ki++) {
    int kt = ktbase + ki;
    const TA* a_lo = Am + (kt * 8 + t4) * 72;
    const TA* a_hi = a_lo + 4 * 72;
    const TB* b_lo = Bm + (kt * 8 + t4) * 72;
    const TB* b_hi = b_lo + 4 * 72;
    uint32_t a[4][4], b[4][2];
#pragma unroll
    for (int mt = 0; mt < 4; mt++) {
      int m = mt * 16 + g;
      a[mt][0] = frag_ld(a_lo + m); a[mt][1] = frag_ld(a_lo + m + 8);
      a[mt][2] = frag_ld(a_hi + m); a[mt][3] = frag_ld(a_hi + m + 8);
    }
#pragma unroll
    for (int nt = 0; nt < 4; nt++) {
      b[nt][0] = frag_ld(b_lo + nt * 8 + g);
      b[nt][1] = frag_ld(b_hi + nt * 8 + g);
    }
#pragma unroll
    for (int mt = 0; mt < 4; mt++)
#pragma unroll
      for (int nt = 0; nt < 4; nt++) mma8(acc[mt][nt], a[mt], b[nt]);
  }
}

// C[m][n] += sum_k A[m][k]*B[k][n]; A row-major stride 68 (pre-cvt u32),
// B k-major stride 72 (pre-cvt u32); full k = 64.
__device__ __forceinline__ void wgemm_a68(const uint32_t* Am, const uint32_t* Bm,
                                          float acc[4][4][4]) {
  int lane = threadIdx.x & 31, g = lane >> 2, t4 = lane & 3;
#pragma unroll
  for (int kt = 0; kt < 8; kt++) {
    uint32_t a[4][4], b[4][2];
#pragma unroll
    for (int mt = 0; mt < 4; mt++) {
      const uint32_t* r_lo = Am + (mt * 16 + g) * 68 + kt * 8;
      const uint32_t* r_hi = r_lo + 8 * 68;
      a[mt][0] = r_lo[t4]; a[mt][1] = r_hi[t4];
      a[mt][2] = r_lo[t4 + 4]; a[mt][3] = r_hi[t4 + 4];
    }
    const uint32_t* b_lo = Bm + (kt * 8 + t4) * 72;
    const uint32_t* b_hi = b_lo + 4 * 72;
#pragma unroll
    for (int nt = 0; nt < 4; nt++) {
      b[nt][0] = b_lo[nt * 8 + g];
      b[nt][1] = b_hi[nt * 8 + g];
    }
#pragma unroll
    for (int mt = 0; mt < 4; mt++)
#pragma unroll
      for (int nt = 0; nt < 4; nt++) mma8(acc[mt][nt], a[mt], b[nt]);
  }
}

// ---------------- scratch globals ---------------------------------------------
__device__ float g_part[BATCH * 128 * 4096];
__device__ float g_G[BATCH * 4096];
__device__ float g_M[BATCH * 4096];   // M natural: [c][e]
__device__ float g_Wpt[4096];         // Wp transposed: [c2][j]

// ---------------- kA: partial G = X^T X ---------------------------------------
// 1024 blocks x 256 thr. Chunk = 512 rows, 4 stages of 128 rows (double-buffered).
// 8 warps = 4 k-groups x 2 n-halves. smem: 2 x 9216 floats = 73728 B.
__global__ void __launch_bounds__(256, 2) kA(const float* __restrict__ x) {
  extern __shared__ float sm[];
  int b = blockIdx.x >> 7, chunk = blockIdx.x & 127;
  const float* Xc = x + (size_t)b * NBF + (size_t)chunk * 32768;
  int t = threadIdx.x, w = t >> 5, lane = t & 31, g = lane >> 2, t4 = lane & 3;
  int q = w >> 1, h = w & 1;
  float acc[4][4][4]; ZERO_ACC4(acc);
#pragma unroll
  for (int i = 0; i < 8; i++) {
    int id = i * 256 + t;
    cp16(&sm[(id >> 4) * 72 + (id & 15) * 4], Xc + id * 4);
  }
  cp_commit();
  for (int s = 0; s < 4; s++) {
    __syncthreads();
    if (s < 3) {
      const float* src = Xc + (s + 1) * 8192;
      float* dst = sm + ((s + 1) & 1) * 9216;
#pragma unroll
      for (int i = 0; i < 8; i++) {
        int id = i * 256 + t;
        cp16(&dst[(id >> 4) * 72 + (id & 15) * 4], src + id * 4);
      }
      cp_commit();
      cp_wait<1>();
    } else {
      cp_wait<0>();
    }
    __syncthreads();
    const float* B = sm + (s & 1) * 9216;
    wgemm_k72<float, float>(B, B + 32 * h, 4 * q, acc);
  }
  __syncthreads();
  // park: 8 warps -> 4 regions (by q), disjoint col-halves (by h)
  float* R = sm + q * 4608;
#pragma unroll
  for (int mt = 0; mt < 4; mt++)
#pragma unroll
    for (int nt = 0; nt < 4; nt++) {
      int col = 32 * h + nt * 8 + 2 * t4;
      int row = mt * 16 + g;
      *reinterpret_cast<float2*>(&R[row * 72 + col]) =
          make_float2(acc[mt][nt][0], acc[mt][nt][1]);
      *reinterpret_cast<float2*>(&R[(row + 8) * 72 + col]) =
          make_float2(acc[mt][nt][2], acc[mt][nt][3]);
    }
  __syncthreads();
  float* P = g_part + (size_t)blockIdx.x * 4096;
#pragma unroll
  for (int i = 0; i < 16; i++) {
    int idx = i * 256 + t;
    int r = idx >> 6, c = idx & 63;
    P[idx] = sm[r * 72 + c] + sm[4608 + r * 72 + c] +
             sm[9216 + r * 72 + c] + sm[13824 + r * 72 + c];
  }
}

// ---------------- kRed: reduce 128 partials per batch ---------------------------
__global__ void __launch_bounds__(256) kRed() {
  int b = blockIdx.x >> 4, s = blockIdx.x & 15;
  int e = s * 256 + threadIdx.x;
  const float* P = g_part + (size_t)b * 128 * 4096 + e;
  float sum = 0.f;
#pragma unroll 8
  for (int k = 0; k < 128; k++) sum += P[(size_t)k * 4096];
  g_G[b * 4096 + e] = sum;
}

// ---------------- kB: attn, topk+softmax, M (fp32, exact) -----------------------
__global__ void __launch_bounds__(256) kB(const float* __restrict__ wqkv,
                                          const float* __restrict__ wproj) {
  int b = blockIdx.x, t = threadIdx.x;
  __shared__ __align__(16) float sG[4096];
  __shared__ __align__(16) float sP[4096];
  __shared__ __align__(16) float sW[4096];
  for (int i = t; i < 4096; i += 256) sG[i] = g_G[b * 4096 + i];
  for (int i = t; i < 4096; i += 256) sW[i] = wqkv[4096 + i];  // Wk
  __syncthreads();
  {
    int e = t >> 2, d0 = (t & 3) * 16;
    float acc[16];
#pragma unroll
    for (int i = 0; i < 16; i++) acc[i] = 0.f;
    for (int f = 0; f < 64; f++) {
      float gg = sG[e * 64 + f];
#pragma unroll
      for (int i = 0; i < 16; i++) acc[i] += gg * sW[(d0 + i) * 64 + f];
    }
#pragma unroll
    for (int i = 0; i < 16; i++) sP[e * 64 + d0 + i] = acc[i];
  }
  __syncthreads();
  for (int i = t; i < 4096; i += 256) sW[i] = wqkv[8192 + i];  // Wv
  __syncthreads();
  {
    int c = t >> 2, d0 = (t & 3) * 16;
    float acc[16];
#pragma unroll
    for (int i = 0; i < 16; i++) acc[i] = 0.f;
    for (int e = 0; e < 64; e++) {
      float wv = sW[c * 64 + e];
#pragma unroll
      for (int i = 0; i < 16; i++) acc[i] += wv * sP[e * 64 + d0 + i];
    }
#pragma unroll
    for (int i = 0; i < 16; i++) sG[c * 64 + d0 + i] = acc[i] * 0.125f;
  }
  __syncthreads();
  if (t < 64) {
    float* row = sG + t * 64;
    u64 drop = 0;
    for (int it = 0; it < 14; it++) {
      float mn = INFINITY; int mi = 0;
      for (int d = 0; d < 64; d++) {
        if ((drop >> d) & 1ULL) continue;
        float v = row[d];
        if (v < mn) { mn = v; mi = d; }
      }
      drop |= 1ULL << mi;
    }
    float mx = -INFINITY;
    for (int d = 0; d < 64; d++)
      if (!((drop >> d) & 1ULL)) mx = fmaxf(mx, row[d]);
    float sum = 0.f;
    for (int d = 0; d < 64; d++) {
      float e = ((drop >> d) & 1ULL) ? 0.f : expf(row[d] - mx);
      row[d] = e; sum += e;
    }
    float inv = 1.f / sum;
    for (int d = 0; d < 64; d++) row[d] *= inv;
  }
  __syncthreads();
  for (int i = t; i < 4096; i += 256) sW[i] = wqkv[i];  // Wq
  __syncthreads();
  {
    int c = t >> 2, e0 = (t & 3) * 16;
    float acc[16];
#pragma unroll
    for (int i = 0; i < 16; i++) acc[i] = 0.f;
    for (int d = 0; d < 64; d++) {
      float a = sG[c * 64 + d];
#pragma unroll
      for (int i = 0; i < 16; i++) acc[i] += a * sW[d * 64 + e0 + i];
    }
#pragma unroll
    for (int i = 0; i < 16; i++) g_M[b * 4096 + c * 64 + e0 + i] = acc[i];
  }
  if (b == 0)
    for (int i = t; i < 4096; i += 256) g_Wpt[i] = wproj[(i & 63) * 64 + (i >> 6)];
}

// ---------------- kC: per (b,p): Y = M (Xblk^T Wp^T) + bp + x (tf32 mma) --------
// 2048 blocks x 256 thr. 8 warps = 4 p-tiles x 2 j-halves.
// smem floats: Xs[4][4608] | sWp[4608] (tf32) | sM[4352] (tf32) = 27392 -> 109568 B.
#define KC_SMEM_BYTES (27392 * 4)
__global__ void __launch_bounds__(256, 2) kC(const float* __restrict__ x,
                                             const float* __restrict__ bproj,
                                             float* __restrict__ y) {
  extern __shared__ float s[];
  int t = threadIdx.x, w = t >> 5, lane = t & 31, g = lane >> 2, t4 = lane & 3;
  int tl = w >> 1, h = w & 1;
  int b = blockIdx.x >> 8, pg = blockIdx.x & 255, p = pg * 4 + tl;
  float* Xs  = s + tl * 4608;
  float* sWp = s + 18432;
  float* sM  = s + 23040;
  const float* xg = x + (size_t)b * NBF + (size_t)p * 4096;
#pragma unroll
  for (int i = 0; i < 16; i++) {
    int id = i * 64 + h * 32 + lane;
    cp16(Xs + (id >> 4) * 72 + (id & 15) * 4, xg + id * 4);
  }
  cp_commit();
  // prefetch residual rows into L2 (consumed in the epilogue)
  {
    const float* base = x + (size_t)b * NBF + ((size_t)p << 6) + h * 32;
    const float* pf0 = base + ((size_t)lane << 16);
    const float* pf1 = base + ((size_t)(lane + 32) << 16);
    asm volatile("prefetch.L2 [%0];" :: "l"(pf0));
    asm volatile("prefetch.L2 [%0];" :: "l"(pf1));
  }
  for (int i = t; i < 4096; i += 256)
    sWp[(i >> 6) * 72 + (i & 63)] = __uint_as_float(cvt_tf32(g_Wpt[i]));
  for (int i = t; i < 4096; i += 256)
    sM[(i >> 6) * 68 + (i & 63)] = __uint_as_float(cvt_tf32(g_M[b * 4096 + i]));
  cp_wait<0>();
  __syncthreads();

  float acc[4][4][4]; ZERO_ACC4(acc);
  const uint32_t* Wq = reinterpret_cast<const uint32_t*>(sWp) + 32 * h;
  wgemm_k72<float, uint32_t>(Xs, Wq, 0, acc);   // D1[e][j] = sum_c2 X[c2][e] WpT[c2][j]
  wgemm_k72<float, uint32_t>(Xs, Wq, 4, acc);
  __syncthreads();  // both tile warps done reading X before D1 overwrites it
#pragma unroll
  for (int mt = 0; mt < 4; mt++)
#pragma unroll
    for (int nt = 0; nt < 4; nt++) {
      int col = 32 * h + nt * 8 + 2 * t4;
      int row = mt * 16 + g;
      *reinterpret_cast<float2*>(&Xs[row * 72 + col]) = make_float2(
          __uint_as_float(cvt_tf32(acc[mt][nt][0])),
          __uint_as_float(cvt_tf32(acc[mt][nt][1])));
      *reinterpret_cast<float2*>(&Xs[(row + 8) * 72 + col]) = make_float2(
          __uint_as_float(cvt_tf32(acc[mt][nt][2])),
          __uint_as_float(cvt_tf32(acc[mt][nt][3])));
    }
  __syncwarp();
  ZERO_ACC4(acc);
  wgemm_a68(reinterpret_cast<const uint32_t*>(sM),
            reinterpret_cast<const uint32_t*>(Xs) + 32 * h, acc);
  // epilogue: y = OUT + bp + x
  const float* xr = x + (size_t)b * NBF;
  float* yr = y + (size_t)b * NBF;
#pragma unroll
  for (int nt = 0; nt < 4; nt++) {
    int j0 = 32 * h + nt * 8 + 2 * t4;
    float2 bp = *reinterpret_cast<const float2*>(bproj + j0);
#pragma unroll
    for (int mt = 0; mt < 4; mt++) {
      int c = mt * 16 + g;
      size_t off = ((size_t)(c * 1024 + p) << 6) + j0;
      float2 xv = *reinterpret_cast<const float2*>(xr + off);
      *reinterpret_cast<float2*>(yr + off) =
          make_float2(acc[mt][nt][0] + bp.x + xv.x, acc[mt][nt][1] + bp.y + xv.y);
      size_t off2 = ((size_t)((c + 8) * 1024 + p) << 6) + j0;
      float2 xv2 = *reinterpret_cast<const float2*>(xr + off2);
      *reinterpret_cast<float2*>(yr + off2) =
          make_float2(acc[mt][nt][2] + bp.x + xv2.x, acc[mt][nt][3] + bp.y + xv2.y);
    }
  }
}

extern "C" void kernel_launch(void* const* d_in, const int* in_sizes, int n_in,
                              void* d_out, int out_size) {
  const float* x     = (const float*)d_in[0];
  const float* wqkv  = (const float*)d_in[1];
  const float* wproj = (const float*)d_in[2];
  const float* bproj = (const float*)d_in[3];
  float* y = (float*)d_out;
  static int smem_set = 0;
  if (!smem_set) {
    cudaFuncSetAttribute(kA, cudaFuncAttributeMaxDynamicSharedMemorySize, 73728);
    cudaFuncSetAttribute(kC, cudaFuncAttributeMaxDynamicSharedMemorySize,
                         KC_SMEM_BYTES);
    smem_set = 1;
  }
  kA<<<1024, 256, 73728>>>(x);
  kRed<<<128, 256>>>();
  kB<<<8, 256>>>(wqkv, wproj);
  kC<<<2048, 256, KC_SMEM_BYTES>>>(x, bproj, y);
}

// round 7
// speedup vs baseline: 1.5500x; 1.1014x over previous
#include <cuda_runtime.h>
#include <math.h>
#include <stdint.h>

#define BATCH 8
#define NBF   4194304   // 65536*64 floats per batch
typedef unsigned long long u64;

// ---------------- async copy helpers -----------------------------------------
__device__ __forceinline__ void cp16(void* smem, const void* gmem) {
  unsigned s = (unsigned)__cvta_generic_to_shared(smem);
  asm volatile("cp.async.cg.shared.global [%0], [%1], 16;" :: "r"(s), "l"(gmem));
}
__device__ __forceinline__ void cp_commit() { asm volatile("cp.async.commit_group;"); }
template<int N> __device__ __forceinline__ void cp_wait() {
  asm volatile("cp.async.wait_group %0;" :: "n"(N));
}

// ---------------- tf32 mma helpers --------------------------------------------
__device__ __forceinline__ uint32_t cvt_tf32(float f) {
  uint32_t r; asm("cvt.rna.tf32.f32 %0, %1;" : "=r"(r) : "f"(f)); return r;
}
__device__ __forceinline__ void mma8(float* c, const uint32_t* a, const uint32_t* b) {
  asm volatile(
      "mma.sync.aligned.m16n8k8.row.col.f32.tf32.tf32.f32 "
      "{%0,%1,%2,%3}, {%4,%5,%6,%7}, {%8,%9}, {%0,%1,%2,%3};"
      : "+f"(c[0]), "+f"(c[1]), "+f"(c[2]), "+f"(c[3])
      : "r"(a[0]), "r"(a[1]), "r"(a[2]), "r"(a[3]), "r"(b[0]), "r"(b[1]));
}
__device__ __forceinline__ uint32_t frag_ld(const float* p)    { return cvt_tf32(*p); }
__device__ __forceinline__ uint32_t frag_ld(const uint32_t* p) { return *p; }

// m16 x n32 GEMM slice: acc[4][4]. A k-major stride 72 (cols m0..m0+15),
// B k-major stride 72 u32 (cols n0..n0+31), k = 64 rows from given bases.
template<typename TA>
__device__ __forceinline__ void wg16x32(const TA* Am, const uint32_t* Bm,
                                        int m0, int n0, float acc[4][4]) {
  int lane = threadIdx.x & 31, g = lane >> 2, t4 = lane & 3;
#pragma unroll
  for (int kt = 0; kt < 8; kt++) {
    const TA* a_lo = Am + (kt * 8 + t4) * 72 + m0;
    const TA* a_hi = a_lo + 4 * 72;
    uint32_t a[4];
    a[0] = frag_ld(a_lo + g);     a[1] = frag_ld(a_lo + g + 8);
    a[2] = frag_ld(a_hi + g);     a[3] = frag_ld(a_hi + g + 8);
    const uint32_t* b_lo = Bm + (kt * 8 + t4) * 72 + n0;
    const uint32_t* b_hi = b_lo + 4 * 72;
#pragma unroll
    for (int nt = 0; nt < 4; nt++) {
      uint32_t b[2] = { b_lo[nt * 8 + g], b_hi[nt * 8 + g] };
      mma8(acc[nt], a, b);
    }
  }
}

// m16 x n32 with row-major A (stride 68, u32): A[m][k].
__device__ __forceinline__ void wg16x32_rA(const uint32_t* Am, const uint32_t* Bm,
                                           int m0, int n0, float acc[4][4]) {
  int lane = threadIdx.x & 31, g = lane >> 2, t4 = lane & 3;
#pragma unroll
  for (int kt = 0; kt < 8; kt++) {
    const uint32_t* r0 = Am + (m0 + g) * 68 + kt * 8;
    const uint32_t* r1 = r0 + 8 * 68;
    uint32_t a[4] = { r0[t4], r1[t4], r0[t4 + 4], r1[t4 + 4] };
    const uint32_t* b_lo = Bm + (kt * 8 + t4) * 72 + n0;
    const uint32_t* b_hi = b_lo + 4 * 72;
#pragma unroll
    for (int nt = 0; nt < 4; nt++) {
      uint32_t b[2] = { b_lo[nt * 8 + g], b_hi[nt * 8 + g] };
      mma8(acc[nt], a, b);
    }
  }
}

// m16 x n64 GEMM slice for kA: acc[8][4]. Both operands u32 k-major stride 72.
__device__ __forceinline__ void wg16x64(const uint32_t* Am, const uint32_t* Bm,
                                        int m0, float acc[8][4]) {
  int lane = threadIdx.x & 31, g = lane >> 2, t4 = lane & 3;
#pragma unroll
  for (int kt = 0; kt < 8; kt++) {
    const uint32_t* a_lo = Am + (kt * 8 + t4) * 72 + m0;
    const uint32_t* a_hi = a_lo + 4 * 72;
    uint32_t a[4] = { a_lo[g], a_lo[g + 8], a_hi[g], a_hi[g + 8] };
    const uint32_t* b_lo = Bm + (kt * 8 + t4) * 72;
    const uint32_t* b_hi = b_lo + 4 * 72;
#pragma unroll
    for (int nt = 0; nt < 8; nt++) {
      uint32_t b[2] = { b_lo[nt * 8 + g], b_hi[nt * 8 + g] };
      mma8(acc[nt], a, b);
    }
  }
}

// ---------------- scratch globals ---------------------------------------------
__device__ float g_part[BATCH * 128 * 4096];
__device__ float g_G[BATCH * 4096];
__device__ float g_M[BATCH * 4096];   // M natural: [c][e]
__device__ float g_Wpt[4096];         // Wp transposed: [c2][j]

// ---------------- kA: partial G = X^T X ---------------------------------------
// 1024 blocks x 256 thr (8 warps = 4 m-slices x 2 k-halves). Chunk = 512 rows,
// 4 double-buffered stages of 128 rows; per-stage tf32 convert pass.
// smem: 2 x 9216 floats = 73728 B -> 3 blocks/SM.
__global__ void __launch_bounds__(256, 3) kA(const float* __restrict__ x) {
  extern __shared__ float sm[];
  int b = blockIdx.x >> 7, chunk = blockIdx.x & 127;
  const float* Xc = x + (size_t)b * NBF + (size_t)chunk * 32768;
  int t = threadIdx.x, w = t >> 5, lane = t & 31, g = lane >> 2, t4 = lane & 3;
  int ms = (w & 3) * 16, h = w >> 2;
  float acc[8][4];
#pragma unroll
  for (int i = 0; i < 8; i++)
#pragma unroll
    for (int q = 0; q < 4; q++) acc[i][q] = 0.f;
#pragma unroll
  for (int i = 0; i < 8; i++) {
    int id = i * 256 + t;
    cp16(&sm[(id >> 4) * 72 + (id & 15) * 4], Xc + id * 4);
  }
  cp_commit();
  for (int s = 0; s < 4; s++) {
    __syncthreads();             // everyone done with the buffer being refilled
    if (s < 3) {
      const float* src = Xc + (s + 1) * 8192;
      float* dst = sm + ((s + 1) & 1) * 9216;
#pragma unroll
      for (int i = 0; i < 8; i++) {
        int id = i * 256 + t;
        cp16(&dst[(id >> 4) * 72 + (id & 15) * 4], src + id * 4);
      }
      cp_commit();
      cp_wait<1>();
    } else {
      cp_wait<0>();
    }
    __syncthreads();             // stage s resident everywhere
    float* buf = sm + (s & 1) * 9216;
    // tf32 convert pass (in place, disjoint per thread)
#pragma unroll
    for (int i = 0; i < 9; i++) {
      float4* p = reinterpret_cast<float4*>(buf) + i * 256 + t;
      float4 v = *p;
      v.x = __uint_as_float(cvt_tf32(v.x)); v.y = __uint_as_float(cvt_tf32(v.y));
      v.z = __uint_as_float(cvt_tf32(v.z)); v.w = __uint_as_float(cvt_tf32(v.w));
      *p = v;
    }
    __syncthreads();
    const uint32_t* bu = reinterpret_cast<const uint32_t*>(buf) + h * 4608;
    wg16x64(bu, bu, ms, acc);
  }
  __syncthreads();
  // park the two k-halves (disjoint regions), then sum into g_part
  float* R = sm + h * 9216;
#pragma unroll
  for (int nt = 0; nt < 8; nt++) {
    int col = nt * 8 + 2 * t4;
    *reinterpret_cast<float2*>(&R[(ms + g) * 72 + col]) =
        make_float2(acc[nt][0], acc[nt][1]);
    *reinterpret_cast<float2*>(&R[(ms + g + 8) * 72 + col]) =
        make_float2(acc[nt][2], acc[nt][3]);
  }
  __syncthreads();
  float* P = g_part + (size_t)blockIdx.x * 4096;
#pragma unroll
  for (int i = 0; i < 16; i++) {
    int idx = i * 256 + t;
    int r = idx >> 6, c = idx & 63;
    P[idx] = sm[r * 72 + c] + sm[9216 + r * 72 + c];
  }
}

// ---------------- kRed: reduce 128 partials per batch ---------------------------
__global__ void __launch_bounds__(256) kRed() {
  int b = blockIdx.x >> 4, s = blockIdx.x & 15;
  int e = s * 256 + threadIdx.x;
  const float* P = g_part + (size_t)b * 128 * 4096 + e;
  float sum = 0.f;
#pragma unroll 8
  for (int k = 0; k < 128; k++) sum += P[(size_t)k * 4096];
  g_G[b * 4096 + e] = sum;
}

// ---------------- kB: attn, topk+softmax, M (fp32, exact) -----------------------
__global__ void __launch_bounds__(256) kB(const float* __restrict__ wqkv,
                                          const float* __restrict__ wproj) {
  int b = blockIdx.x, t = threadIdx.x;
  __shared__ __align__(16) float sG[4096];
  __shared__ __align__(16) float sP[4096];
  __shared__ __align__(16) float sW[4096];
  for (int i = t; i < 4096; i += 256) sG[i] = g_G[b * 4096 + i];
  for (int i = t; i < 4096; i += 256) sW[i] = wqkv[4096 + i];  // Wk
  __syncthreads();
  {
    int e = t >> 2, d0 = (t & 3) * 16;
    float acc[16];
#pragma unroll
    for (int i = 0; i < 16; i++) acc[i] = 0.f;
    for (int f = 0; f < 64; f++) {
      float gg = sG[e * 64 + f];
#pragma unroll
      for (int i = 0; i < 16; i++) acc[i] += gg * sW[(d0 + i) * 64 + f];
    }
#pragma unroll
    for (int i = 0; i < 16; i++) sP[e * 64 + d0 + i] = acc[i];
  }
  __syncthreads();
  for (int i = t; i < 4096; i += 256) sW[i] = wqkv[8192 + i];  // Wv
  __syncthreads();
  {
    int c = t >> 2, d0 = (t & 3) * 16;
    float acc[16];
#pragma unroll
    for (int i = 0; i < 16; i++) acc[i] = 0.f;
    for (int e = 0; e < 64; e++) {
      float wv = sW[c * 64 + e];
#pragma unroll
      for (int i = 0; i < 16; i++) acc[i] += wv * sP[e * 64 + d0 + i];
    }
#pragma unroll
    for (int i = 0; i < 16; i++) sG[c * 64 + d0 + i] = acc[i] * 0.125f;
  }
  __syncthreads();
  if (t < 64) {
    float* row = sG + t * 64;
    u64 drop = 0;
    for (int it = 0; it < 14; it++) {
      float mn = INFINITY; int mi = 0;
      for (int d = 0; d < 64; d++) {
        if ((drop >> d) & 1ULL) continue;
        float v = row[d];
        if (v < mn) { mn = v; mi = d; }
      }
      drop |= 1ULL << mi;
    }
    float mx = -INFINITY;
    for (int d = 0; d < 64; d++)
      if (!((drop >> d) & 1ULL)) mx = fmaxf(mx, row[d]);
    float sum = 0.f;
    for (int d = 0; d < 64; d++) {
      float e = ((drop >> d) & 1ULL) ? 0.f : expf(row[d] - mx);
      row[d] = e; sum += e;
    }
    float inv = 1.f / sum;
    for (int d = 0; d < 64; d++) row[d] *= inv;
  }
  __syncthreads();
  for (int i = t; i < 4096; i += 256) sW[i] = wqkv[i];  // Wq
  __syncthreads();
  {
    int c = t >> 2, e0 = (t & 3) * 16;
    float acc[16];
#pragma unroll
    for (int i = 0; i < 16; i++) acc[i] = 0.f;
    for (int d = 0; d < 64; d++) {
      float a = sG[c * 64 + d];
#pragma unroll
      for (int i = 0; i < 16; i++) acc[i] += a * sW[d * 64 + e0 + i];
    }
#pragma unroll
    for (int i = 0; i < 16; i++) g_M[b * 4096 + c * 64 + e0 + i] = acc[i];
  }
  if (b == 0)
    for (int i = t; i < 4096; i += 256) g_Wpt[i] = wproj[(i & 63) * 64 + (i >> 6)];
}

// ---------------- kC: per (b,p): Y = M (Xblk^T Wp^T) + bp + x -------------------
// 1024 blocks x 256 thr; 8 p-tiles per block, double-buffered; 8 warps cooperate
// per tile (4 m-slices x 2 n-halves).
// smem floats: Xbuf 2x4608 | Wp u32 4608 (stride 72) | M u32 4352 (stride 68)
//            = 18176 floats = 72704 B -> 3 blocks/SM.
#define KC_SMEM_BYTES (18176 * 4)
__global__ void __launch_bounds__(256, 3) kC(const float* __restrict__ x,
                                             const float* __restrict__ bproj,
                                             float* __restrict__ y) {
  extern __shared__ float s[];
  uint32_t* sWp = reinterpret_cast<uint32_t*>(s + 9216);
  uint32_t* sM  = reinterpret_cast<uint32_t*>(s + 13824);
  int t = threadIdx.x, w = t >> 5, lane = t & 31, g = lane >> 2, t4 = lane & 3;
  int ms = (w & 3) * 16, nh = (w >> 2) * 32;
  int b = blockIdx.x >> 7, grp = blockIdx.x & 127;
  const float* xbase = x + (size_t)b * NBF;
  // weights (once per block)
  for (int i = t; i < 4096; i += 256) sWp[(i >> 6) * 72 + (i & 63)] = cvt_tf32(g_Wpt[i]);
  for (int i = t; i < 4096; i += 256) sM[(i >> 6) * 68 + (i & 63)] = cvt_tf32(g_M[b * 4096 + i]);
  // preload tile 0
  {
    const float* src = xbase + (size_t)(grp * 8) * 4096;
#pragma unroll
    for (int i = 0; i < 4; i++) {
      int id = i * 256 + t;
      cp16(&s[(id >> 4) * 72 + (id & 15) * 4], src + id * 4);
    }
    cp_commit();
  }
  for (int it = 0; it < 8; it++) {
    int p = grp * 8 + it;
    __syncthreads();             // D1 of iter it-2 fully consumed; buffer free
    if (it < 7) {
      const float* src = xbase + (size_t)(p + 1) * 4096;
      float* dst = s + ((it + 1) & 1) * 4608;
#pragma unroll
      for (int i = 0; i < 4; i++) {
        int id = i * 256 + t;
        cp16(&dst[(id >> 4) * 72 + (id & 15) * 4], src + id * 4);
      }
      cp_commit();
      cp_wait<1>();
    } else {
      cp_wait<0>();
    }
    __syncthreads();             // tile it resident
    float* Xb = s + (it & 1) * 4608;
    // GEMM1: D1[e,j] = sum_c2 X[c2,e] * WpT[c2,j]
    float acc[4][4];
#pragma unroll
    for (int i = 0; i < 4; i++)
#pragma unroll
      for (int q = 0; q < 4; q++) acc[i][q] = 0.f;
    wg16x32<float>(Xb, sWp, ms, nh, acc);
    __syncthreads();             // all X reads done before overwrite
    // store D1 (tf32 bits) in place
    uint32_t* D1 = reinterpret_cast<uint32_t*>(Xb);
#pragma unroll
    for (int nt = 0; nt < 4; nt++) {
      int col = nh + nt * 8 + 2 * t4;
      uint2 v0 = make_uint2(cvt_tf32(acc[nt][0]), cvt_tf32(acc[nt][1]));
      uint2 v1 = make_uint2(cvt_tf32(acc[nt][2]), cvt_tf32(acc[nt][3]));
      *reinterpret_cast<uint2*>(&D1[(ms + g) * 72 + col]) = v0;
      *reinterpret_cast<uint2*>(&D1[(ms + g + 8) * 72 + col]) = v1;
    }
    __syncthreads();             // D1 visible
    // GEMM2: OUT[c,j] = sum_e M[c,e] * D1[e,j]
#pragma unroll
    for (int i = 0; i < 4; i++)
#pragma unroll
      for (int q = 0; q < 4; q++) acc[i][q] = 0.f;
    wg16x32_rA(sM, D1, ms, nh, acc);
    // epilogue: y = OUT + bp + x  (rows c*1024+p)
    float* yr = y + (size_t)b * NBF;
#pragma unroll
    for (int nt = 0; nt < 4; nt++) {
      int j0 = nh + nt * 8 + 2 * t4;
      float2 bp = *reinterpret_cast<const float2*>(bproj + j0);
      int c0 = ms + g, c1 = ms + g + 8;
      size_t off0 = ((size_t)(c0 * 1024 + p) << 6) + j0;
      size_t off1 = ((size_t)(c1 * 1024 + p) << 6) + j0;
      float2 x0 = *reinterpret_cast<const float2*>(xbase + off0);
      float2 x1 = *reinterpret_cast<const float2*>(xbase + off1);
      *reinterpret_cast<float2*>(yr + off0) =
          make_float2(acc[nt][0] + bp.x + x0.x, acc[nt][1] + bp.y + x0.y);
      *reinterpret_cast<float2*>(yr + off1) =
          make_float2(acc[nt][2] + bp.x + x1.x, acc[nt][3] + bp.y + x1.y);
    }
  }
}

extern "C" void kernel_launch(void* const* d_in, const int* in_sizes, int n_in,
                              void* d_out, int out_size) {
  const float* x     = (const float*)d_in[0];
  const float* wqkv  = (const float*)d_in[1];
  const float* wproj = (const float*)d_in[2];
  const float* bproj = (const float*)d_in[3];
  float* y = (float*)d_out;
  static int smem_set = 0;
  if (!smem_set) {
    cudaFuncSetAttribute(kA, cudaFuncAttributeMaxDynamicSharedMemorySize, 73728);
    cudaFuncSetAttribute(kC, cudaFuncAttributeMaxDynamicSharedMemorySize,
                         KC_SMEM_BYTES);
    smem_set = 1;
  }
  kA<<<1024, 256, 73728>>>(x);
  kRed<<<128, 256>>>();
  kB<<<8, 256>>>(wqkv, wproj);
  kC<<<1024, 256, KC_SMEM_BYTES>>>(x, bproj, y);
}

// round 8
// speedup vs baseline: 1.7622x; 1.1369x over previous
#include <cuda_runtime.h>
#include <math.h>
#include <stdint.h>

#define BATCH 8
#define NBF   4194304   // 65536*64 floats per batch
typedef unsigned long long u64;

// ---------------- bf16 mma helpers ---------------------------------------------
__device__ __forceinline__ uint32_t pkb(float lo, float hi) {
  uint32_t r;
  asm("cvt.rn.bf16x2.f32 %0, %1, %2;" : "=r"(r) : "f"(hi), "f"(lo));
  return r;
}
__device__ __forceinline__ void mma16(float* c, const uint32_t* a, const uint32_t* b) {
  asm volatile(
      "mma.sync.aligned.m16n8k16.row.col.f32.bf16.bf16.f32 "
      "{%0,%1,%2,%3}, {%4,%5,%6,%7}, {%8,%9}, {%0,%1,%2,%3};"
      : "+f"(c[0]), "+f"(c[1]), "+f"(c[2]), "+f"(c[3])
      : "r"(a[0]), "r"(a[1]), "r"(a[2]), "r"(a[3]), "r"(b[0]), "r"(b[1]));
}

// ---------------- scratch globals -----------------------------------------------
__device__ float    g_part[BATCH * 128 * 4096];
__device__ float    g_G[BATCH * 4096];
__device__ uint32_t g_MPk[BATCH * 2048];  // M packed bf16x2: [c][ep], pairs along e
__device__ uint32_t g_WpPk[2048];         // Wp^T packed: [c2p][j], pairs along c2

// ---------------- kA: partial G = X^T X (bf16 mma) -------------------------------
// 1024 blocks x 256 thr (8 warps = 4 m-slices x 2 k-halves). Chunk = 512 rows,
// 8 stages of 64 rows; gmem->reg prefetch, pack to bf16x2 smem; 1 sync/stage.
// dyn smem: 9216 u32 = 36864 B (pk double buffer 2x2304 aliased with fp32 park).
__global__ void __launch_bounds__(256, 3) kA(const float* __restrict__ x) {
  extern __shared__ uint32_t dsm[];
  uint32_t* pkbuf = dsm;                           // [2][2304]
  float* park = reinterpret_cast<float*>(dsm);     // aliases (used after loop)
  int b = blockIdx.x >> 7, chunk = blockIdx.x & 127;
  const float* Xc = x + (size_t)b * NBF + (size_t)chunk * 32768;
  int t = threadIdx.x, w = t >> 5, lane = t & 31, g = lane >> 2, t4 = lane & 3;
  int ms = (w & 3) * 16, h = w >> 2;
  int kp = t >> 3, c0 = (t & 7) * 8;
  const float* src = Xc + kp * 128 + c0;
  float4 p0 = *(const float4*)(src);
  float4 p1 = *(const float4*)(src + 64);
  float4 p2 = *(const float4*)(src + 4);
  float4 p3 = *(const float4*)(src + 68);
  float acc[8][4];
#pragma unroll
  for (int i = 0; i < 8; i++)
#pragma unroll
    for (int q = 0; q < 4; q++) acc[i][q] = 0.f;

  for (int s = 0; s < 8; s++) {
    uint32_t* dst = pkbuf + (s & 1) * 2304 + kp * 72 + c0;
    *(uint4*)dst = make_uint4(pkb(p0.x, p1.x), pkb(p0.y, p1.y),
                              pkb(p0.z, p1.z), pkb(p0.w, p1.w));
    *(uint4*)(dst + 4) = make_uint4(pkb(p2.x, p3.x), pkb(p2.y, p3.y),
                                    pkb(p2.z, p3.z), pkb(p2.w, p3.w));
    __syncthreads();
    if (s < 7) {
      const float* ns = Xc + (s + 1) * 4096 + kp * 128 + c0;
      p0 = *(const float4*)(ns);      p1 = *(const float4*)(ns + 64);
      p2 = *(const float4*)(ns + 4);  p3 = *(const float4*)(ns + 68);
    }
    const uint32_t* B = pkbuf + (s & 1) * 2304;
#pragma unroll
    for (int ki = 0; ki < 2; ki++) {
      int kt = 2 * h + ki;
      const uint32_t* r_lo = B + (kt * 8 + t4) * 72;
      const uint32_t* r_hi = r_lo + 288;
      uint32_t a[4] = { r_lo[ms + g], r_lo[ms + g + 8], r_hi[ms + g], r_hi[ms + g + 8] };
#pragma unroll
      for (int nt = 0; nt < 8; nt++) {
        uint32_t bb[2] = { r_lo[nt * 8 + g], r_hi[nt * 8 + g] };
        mma16(acc[nt], a, bb);
      }
    }
  }
  __syncthreads();
  // park fp32 partials per k-half, then sum to g_part
  float* Ph = park + h * 4608;
#pragma unroll
  for (int nt = 0; nt < 8; nt++) {
    int col = nt * 8 + 2 * t4;
    *(float2*)&Ph[(ms + g) * 72 + col]     = make_float2(acc[nt][0], acc[nt][1]);
    *(float2*)&Ph[(ms + g + 8) * 72 + col] = make_float2(acc[nt][2], acc[nt][3]);
  }
  __syncthreads();
  float* P = g_part + (size_t)blockIdx.x * 4096;
#pragma unroll
  for (int i = 0; i < 16; i++) {
    int idx = i * 256 + t, r = idx >> 6, c = idx & 63;
    P[idx] = park[r * 72 + c] + park[4608 + r * 72 + c];
  }
}

// ---------------- kRed: reduce 128 partials per batch ----------------------------
__global__ void __launch_bounds__(256) kRed() {
  int b = blockIdx.x >> 4, s = blockIdx.x & 15;
  int e = s * 256 + threadIdx.x;
  const float* P = g_part + (size_t)b * 128 * 4096 + e;
  float sum = 0.f;
#pragma unroll 8
  for (int k = 0; k < 128; k++) sum += P[(size_t)k * 4096];
  g_G[b * 4096 + e] = sum;
}

// ---------------- kB: attn, topk+softmax, M (fp32, exact) ------------------------
__global__ void __launch_bounds__(256) kB(const float* __restrict__ wqkv,
                                          const float* __restrict__ wproj) {
  int b = blockIdx.x, t = threadIdx.x;
  __shared__ __align__(16) float sG[4096];
  __shared__ __align__(16) float sP[4096];
  __shared__ __align__(16) float sW[4096];
  for (int i = t; i < 4096; i += 256) sG[i] = g_G[b * 4096 + i];
  for (int i = t; i < 4096; i += 256) sW[i] = wqkv[4096 + i];  // Wk
  __syncthreads();
  {
    int e = t >> 2, d0 = (t & 3) * 16;
    float acc[16];
#pragma unroll
    for (int i = 0; i < 16; i++) acc[i] = 0.f;
    for (int f = 0; f < 64; f++) {
      float gg = sG[e * 64 + f];
#pragma unroll
      for (int i = 0; i < 16; i++) acc[i] += gg * sW[(d0 + i) * 64 + f];
    }
#pragma unroll
    for (int i = 0; i < 16; i++) sP[e * 64 + d0 + i] = acc[i];
  }
  __syncthreads();
  for (int i = t; i < 4096; i += 256) sW[i] = wqkv[8192 + i];  // Wv
  __syncthreads();
  {
    int c = t >> 2, d0 = (t & 3) * 16;
    float acc[16];
#pragma unroll
    for (int i = 0; i < 16; i++) acc[i] = 0.f;
    for (int e = 0; e < 64; e++) {
      float wv = sW[c * 64 + e];
#pragma unroll
      for (int i = 0; i < 16; i++) acc[i] += wv * sP[e * 64 + d0 + i];
    }
#pragma unroll
    for (int i = 0; i < 16; i++) sG[c * 64 + d0 + i] = acc[i] * 0.125f;
  }
  __syncthreads();
  if (t < 64) {
    float* row = sG + t * 64;
    u64 drop = 0;
    for (int it = 0; it < 14; it++) {
      float mn = INFINITY; int mi = 0;
      for (int d = 0; d < 64; d++) {
        if ((drop >> d) & 1ULL) continue;
        float v = row[d];
        if (v < mn) { mn = v; mi = d; }
      }
      drop |= 1ULL << mi;
    }
    float mx = -INFINITY;
    for (int d = 0; d < 64; d++)
      if (!((drop >> d) & 1ULL)) mx = fmaxf(mx, row[d]);
    float sum = 0.f;
    for (int d = 0; d < 64; d++) {
      float e = ((drop >> d) & 1ULL) ? 0.f : expf(row[d] - mx);
      row[d] = e; sum += e;
    }
    float inv = 1.f / sum;
    for (int d = 0; d < 64; d++) row[d] *= inv;
  }
  __syncthreads();
  for (int i = t; i < 4096; i += 256) sW[i] = wqkv[i];  // Wq
  __syncthreads();
  {
    int c = t >> 2, e0 = (t & 3) * 16;
    float acc[16];
#pragma unroll
    for (int i = 0; i < 16; i++) acc[i] = 0.f;
    for (int d = 0; d < 64; d++) {
      float a = sG[c * 64 + d];
#pragma unroll
      for (int i = 0; i < 16; i++) acc[i] += a * sW[d * 64 + e0 + i];
    }
    // pack M -> bf16x2 pairs along e
#pragma unroll
    for (int i = 0; i < 8; i++)
      g_MPk[b * 2048 + c * 32 + (e0 >> 1) + i] = pkb(acc[2 * i], acc[2 * i + 1]);
  }
  if (b == 0) {
    for (int i = t; i < 2048; i += 256) {
      int c2p = i >> 6, j = i & 63;
      g_WpPk[i] = pkb(wproj[j * 64 + 2 * c2p], wproj[j * 64 + 2 * c2p + 1]);
    }
  }
}

// ---------------- kC: per (b,p): Y = M (Xblk^T Wp^T) + bp + x (bf16 mma) ----------
// 1024 blocks x 256 thr; 8 p-tiles per block; 8 warps = 4 m-slices x 2 n-halves.
// static smem: 3 x 2304 u32 = 27648 B.
__global__ void __launch_bounds__(256, 3) kC(const float* __restrict__ x,
                                             const float* __restrict__ bproj,
                                             float* __restrict__ y) {
  __shared__ uint32_t sX[2304];    // packed X, later packed D1
  __shared__ uint32_t sWp[2304];
  __shared__ uint32_t sMp[2304];
  int t = threadIdx.x, w = t >> 5, lane = t & 31, g = lane >> 2, t4 = lane & 3;
  int ms = (w & 3) * 16, nh = (w >> 2) * 32;
  int b = blockIdx.x >> 7, grp = blockIdx.x & 127;
  const float* xbase = x + (size_t)b * NBF;
  float* yb = y + (size_t)b * NBF;
  for (int i = t; i < 2048; i += 256) sWp[(i >> 6) * 72 + (i & 63)] = g_WpPk[i];
  for (int i = t; i < 2048; i += 256) sMp[(i >> 5) * 36 + (i & 31)] = g_MPk[b * 2048 + i];
  int kp = t >> 3, c0 = (t & 7) * 8;
  const float* src0 = xbase + (size_t)(grp * 8) * 4096 + kp * 128 + c0;
  float4 p0 = *(const float4*)(src0);
  float4 p1 = *(const float4*)(src0 + 64);
  float4 p2 = *(const float4*)(src0 + 4);
  float4 p3 = *(const float4*)(src0 + 68);

  for (int it = 0; it < 8; it++) {
    int p = grp * 8 + it;
    uint32_t* dst = sX + kp * 72 + c0;
    *(uint4*)dst = make_uint4(pkb(p0.x, p1.x), pkb(p0.y, p1.y),
                              pkb(p0.z, p1.z), pkb(p0.w, p1.w));
    *(uint4*)(dst + 4) = make_uint4(pkb(p2.x, p3.x), pkb(p2.y, p3.y),
                                    pkb(p2.z, p3.z), pkb(p2.w, p3.w));
    __syncthreads();
    if (it < 7) {
      const float* ns = xbase + (size_t)(p + 1) * 4096 + kp * 128 + c0;
      p0 = *(const float4*)(ns);      p1 = *(const float4*)(ns + 64);
      p2 = *(const float4*)(ns + 4);  p3 = *(const float4*)(ns + 68);
      if (t < 128) {  // L2 prefetch next residual rows
        const float* pf = xbase + (((size_t)(t >> 1) * 1024 + p + 1) << 6) + (t & 1) * 32;
        asm volatile("prefetch.L2 [%0];" :: "l"(pf));
      }
    }
    // GEMM1: D1[e,j] = sum_c2 X[c2,e] * WpT[c2,j]
    float acc[4][4];
#pragma unroll
    for (int i = 0; i < 4; i++)
#pragma unroll
      for (int q = 0; q < 4; q++) acc[i][q] = 0.f;
#pragma unroll
    for (int kt = 0; kt < 4; kt++) {
      const uint32_t* a_lo = sX + (kt * 8 + t4) * 72;
      const uint32_t* a_hi = a_lo + 288;
      uint32_t a[4] = { a_lo[ms + g], a_lo[ms + g + 8], a_hi[ms + g], a_hi[ms + g + 8] };
      const uint32_t* b_lo = sWp + (kt * 8 + t4) * 72 + nh;
      const uint32_t* b_hi = b_lo + 288;
#pragma unroll
      for (int nt = 0; nt < 4; nt++) {
        uint32_t bb[2] = { b_lo[nt * 8 + g], b_hi[nt * 8 + g] };
        mma16(acc[nt], a, bb);
      }
    }
    __syncthreads();
    // pack D1 -> sX (pairs along e via lane-pair shuffle); even-g lanes store
#pragma unroll
    for (int nt = 0; nt < 4; nt++) {
      float o0 = __shfl_xor_sync(0xffffffffu, acc[nt][0], 4);
      float o1 = __shfl_xor_sync(0xffffffffu, acc[nt][1], 4);
      float o2 = __shfl_xor_sync(0xffffffffu, acc[nt][2], 4);
      float o3 = __shfl_xor_sync(0xffffffffu, acc[nt][3], 4);
      if (!(g & 1)) {
        int j = nh + nt * 8 + 2 * t4;
        int kp0 = (ms + g) >> 1, kp8 = kp0 + 4;
        sX[kp0 * 72 + j]     = pkb(acc[nt][0], o0);
        sX[kp0 * 72 + j + 1] = pkb(acc[nt][1], o1);
        sX[kp8 * 72 + j]     = pkb(acc[nt][2], o2);
        sX[kp8 * 72 + j + 1] = pkb(acc[nt][3], o3);
      }
    }
    __syncthreads();
    // GEMM2: OUT[c,j] = sum_e M[c,e] * D1[e,j]
    float oc[4][4];
#pragma unroll
    for (int i = 0; i < 4; i++)
#pragma unroll
      for (int q = 0; q < 4; q++) oc[i][q] = 0.f;
#pragma unroll
    for (int kt = 0; kt < 4; kt++) {
      const uint32_t* r0 = sMp + (ms + g) * 36 + kt * 8;
      const uint32_t* r1 = r0 + 8 * 36;
      uint32_t a[4] = { r0[t4], r1[t4], r0[t4 + 4], r1[t4 + 4] };
      const uint32_t* b_lo = sX + (kt * 8 + t4) * 72 + nh;
      const uint32_t* b_hi = b_lo + 288;
#pragma unroll
      for (int nt = 0; nt < 4; nt++) {
        uint32_t bb[2] = { b_lo[nt * 8 + g], b_hi[nt * 8 + g] };
        mma16(oc[nt], a, bb);
      }
    }
    // epilogue: y = OUT + bp + x
#pragma unroll
    for (int nt = 0; nt < 4; nt++) {
      int j0 = nh + nt * 8 + 2 * t4;
      float2 bp = *(const float2*)(bproj + j0);
      int cr0 = ms + g, cr1 = ms + g + 8;
      size_t off0 = ((size_t)(cr0 * 1024 + p) << 6) + j0;
      size_t off1 = ((size_t)(cr1 * 1024 + p) << 6) + j0;
      float2 x0 = *(const float2*)(xbase + off0);
      float2 x1 = *(const float2*)(xbase + off1);
      *(float2*)(yb + off0) = make_float2(oc[nt][0] + bp.x + x0.x, oc[nt][1] + bp.y + x0.y);
      *(float2*)(yb + off1) = make_float2(oc[nt][2] + bp.x + x1.x, oc[nt][3] + bp.y + x1.y);
    }
    __syncthreads();
  }
}

extern "C" void kernel_launch(void* const* d_in, const int* in_sizes, int n_in,
                              void* d_out, int out_size) {
  const float* x     = (const float*)d_in[0];
  const float* wqkv  = (const float*)d_in[1];
  const float* wproj = (const float*)d_in[2];
  const float* bproj = (const float*)d_in[3];
  float* y = (float*)d_out;
  kA<<<1024, 256, 36864>>>(x);
  kRed<<<128, 256>>>();
  kB<<<8, 256>>>(wqkv, wproj);
  kC<<<1024, 256>>>(x, bproj, y);
}